// round 4
// baseline (speedup 1.0000x reference)
#include <cuda_runtime.h>
#include <cstdint>

// Differentiable A* forward, N=4096, Tmax=N/4. Single persistent block, 256 thr.
// Registers: cached selection keys (exp bits), 16 nodes/thread. One BAR/iter.
// Cross-warp tie-break by lane order (warp id order == index order), so the
// block combine is redux32+ballot+shfl instead of a u64 shfl butterfly
// (cuts MIO-pipe pressure ~8x vs previous round).

#define NMAX 4096
#define TPB  256
#define VPT  16         // nodes per thread

__global__ __launch_bounds__(TPB, 1)
void astar_persistent_kernel(const int* __restrict__ start_p,
                             const int* __restrict__ goal_p,
                             const float* __restrict__ h_in,
                             const float* __restrict__ wadj,
                             float* __restrict__ out,
                             int N)
{
    __shared__ float          sm_g[NMAX];
    __shared__ unsigned short sm_par[NMAX];
    __shared__ uint2          sm_warp[2][32];   // (vmax, bestj) per warp, x2 parity

    const int tid  = threadIdx.x;
    const int lane = tid & 31;
    const int wid  = tid >> 5;                  // 0..7
    const int start = start_p[0];
    const int goal  = goal_p[0];
    const float inv_sqrt_n = 1.0f / sqrtf((float)N);   // exactly 1/64 for N=4096
    const int Tmax = N / 4;
    const int j0 = tid * VPT;

    if (tid < 64) reinterpret_cast<uint2*>(sm_warp)[tid] = make_uint2(0u, 0u);

    // ---- init: g0 = wadj[start] row (diag zeroed), open = {start} ----
    float    h16[VPT];
    unsigned val[VPT];           // key = bits of expf(-f/64) if open else 0
    unsigned openm = 0, histm = 0;
    {
        const float4* h4p = reinterpret_cast<const float4*>(h_in);
        const float4* g4p = reinterpret_cast<const float4*>(wadj + (size_t)start * N);
        #pragma unroll
        for (int q = 0; q < 4; q++) {
            float4 hv = h4p[tid * 4 + q];
            float4 gv = g4p[tid * 4 + q];
            float hh[4] = {hv.x, hv.y, hv.z, hv.w};
            float gg[4] = {gv.x, gv.y, gv.z, gv.w};
            #pragma unroll
            for (int r = 0; r < 4; r++) {
                int k = q * 4 + r, j = j0 + k;
                float g = (j == start) ? 0.0f : gg[r];
                h16[k]  = hh[r];
                sm_g[j] = g;
                sm_par[j] = (unsigned short)goal;     // parents0 = goal
                val[k] = 0u;
                if (j == start) {
                    openm |= 1u << k;
                    val[k] = __float_as_uint(
                        expf(-(0.5f * g + 0.5f * h16[k]) * inv_sqrt_n));
                }
            }
        }
    }
    __syncthreads();

    bool done = false;
    int  t_final = 0;

    for (int t = 0; t < Tmax; t++) {
        // ---- lane-local best: explicit tree, earlier index wins ties ----
        unsigned v8[8]; int k8[8];
        #pragma unroll
        for (int i = 0; i < 8; i++) {
            bool gt = val[2*i + 1] > val[2*i];
            v8[i] = gt ? val[2*i + 1] : val[2*i];
            k8[i] = gt ? (2*i + 1) : (2*i);
        }
        unsigned v4[4]; int k4[4];
        #pragma unroll
        for (int i = 0; i < 4; i++) {
            bool gt = v8[2*i + 1] > v8[2*i];
            v4[i] = gt ? v8[2*i + 1] : v8[2*i];
            k4[i] = gt ? k8[2*i + 1] : k8[2*i];
        }
        unsigned v2[2]; int k2[2];
        #pragma unroll
        for (int i = 0; i < 2; i++) {
            bool gt = v4[2*i + 1] > v4[2*i];
            v2[i] = gt ? v4[2*i + 1] : v4[2*i];
            k2[i] = gt ? k4[2*i + 1] : k4[2*i];
        }
        bool gtf = v2[1] > v2[0];
        unsigned bestv = gtf ? v2[1] : v2[0];
        int      bestj = j0 + (gtf ? k2[1] : k2[0]);

        // ---- warp max (lane order == index order => ffs gives lowest j) ----
        unsigned vmax = __reduce_max_sync(0xFFFFFFFFu, bestv);
        unsigned mk   = __ballot_sync(0xFFFFFFFFu, bestv == vmax);
        int wj = __shfl_sync(0xFFFFFFFFu, bestj, __ffs(mk) - 1);
        if (lane == 0) sm_warp[t & 1][wid] = make_uint2(vmax, (unsigned)wj);

        __syncthreads();   // the ONLY barrier per iteration

        // ---- block combine: warp order == index order, same trick ----
        uint2 e = sm_warp[t & 1][lane];              // lanes 8..31 read zeros
        unsigned gv = __reduce_max_sync(0xFFFFFFFFu, e.x);
        unsigned bm = __ballot_sync(0xFFFFFFFFu, e.x == gv);
        const int ind = (int)__shfl_sync(0xFFFFFFFFu, e.y, __ffs(bm) - 1);
        // all-zero (empty open) => ballot all-true => lane 0 => warp0 bestj = 0,
        // matching reference argmax-of-zeros fallback.

        // ---- fetch selected row (L2-warm across graph replays) ----
        const float g_ind = sm_g[ind];
        const float4* row4 = reinterpret_cast<const float4*>(wadj + (size_t)ind * N);
        float4 wv0 = row4[tid * 4 + 0];
        float4 wv1 = row4[tid * 4 + 1];
        float4 wv2 = row4[tid * 4 + 2];
        float4 wv3 = row4[tid * 4 + 3];
        float w16[VPT] = {wv0.x, wv0.y, wv0.z, wv0.w,
                          wv1.x, wv1.y, wv1.z, wv1.w,
                          wv2.x, wv2.y, wv2.z, wv2.w,
                          wv3.x, wv3.y, wv3.z, wv3.w};

        t_final = t;
        if (ind == goal) done = true;

        // ---- close ind + relax (idx == neighbor == (w!=0) & !open & !hist) ----
        #pragma unroll
        for (int k = 0; k < VPT; k++) {
            int j = j0 + k;
            if (j == ind) {
                openm &= ~(1u << k);                 // open2
                histm |=  (1u << k);                 // hist2
                val[k] = 0u;
            } else if (w16[k] != 0.0f &&
                       !((openm >> k) & 1u) && !((histm >> k) & 1u)) {
                float gn = g_ind + w16[k];           // g2 = g[ind] + wadj[ind,j]
                sm_g[j]   = gn;
                sm_par[j] = (unsigned short)ind;
                val[k] = __float_as_uint(
                    expf(-(0.5f * gn + 0.5f * h16[k]) * inv_sqrt_n));
                openm |= 1u << k;                    // open3
            }
        }

        if (done) break;   // uniform; state frozen after goal found
    }

    __syncthreads();       // drain final sm_par writes before readout/backtrack

    // ---- outputs: [0,N) hist, [N,2N) path_maps ----
    #pragma unroll
    for (int k = 0; k < VPT; k++) {
        int j = j0 + k;
        out[j]     = ((histm >> k) & 1u) ? 1.0f : 0.0f;
        out[N + j] = 0.0f;
    }
    __syncthreads();

    if (tid == 0) {
        out[N + goal] = 1.0f;                        // path0 = goal one-hot
        int loc = sm_par[goal];
        for (int i = 0; i < t_final; i++) {
            out[N + loc] = 1.0f;
            loc = sm_par[loc];
        }
    }
}

extern "C" void kernel_launch(void* const* d_in, const int* in_sizes, int n_in,
                              void* d_out, int out_size)
{
    const int*   start = (const int*)  d_in[0];
    const int*   goal  = (const int*)  d_in[1];
    const float* h     = (const float*)d_in[2];
    // d_in[3] = nodes (unused), d_in[4] = adj (redundant with wadj != 0)
    const float* wadj  = (const float*)d_in[5];
    float* out = (float*)d_out;
    int N = in_sizes[2];                             // 4096

    astar_persistent_kernel<<<1, TPB>>>(start, goal, h, wadj, out, N);
}

// round 5
// speedup vs baseline: 1.9005x; 1.9005x over previous
#include <cuda_runtime.h>
#include <cstdint>

// Differentiable A* forward, N=4096, Tmax=N/4. Single persistent block, 1024 thr
// (32 warps — full occupancy is required for latency hiding, per R4 regression).
// One __syncthreads per iteration. Reduction: warp redux+ballot -> predicated
// STS of (vmax,bestj); block combine = 1 LDS.64 + redux32 + ballot + 1 shfl
// (replaces the 10-SHFL u64 butterfly; index-order tie-breaking by lane/warp
// position). Cached exp keys: MUFU only fires on relaxed nodes.

#define NMAX 4096
#define TPB  1024
#define VPT  4          // nodes per thread

__global__ __launch_bounds__(TPB, 1)
void astar_persistent_kernel(const int* __restrict__ start_p,
                             const int* __restrict__ goal_p,
                             const float* __restrict__ h_in,
                             const float* __restrict__ wadj,
                             float* __restrict__ out,
                             int N)
{
    __shared__ float          sm_g[NMAX];
    __shared__ unsigned short sm_par[NMAX];
    __shared__ __align__(16) uint2 sm_warp[2][32];   // (vmax, bestj), x2 parity

    const int tid  = threadIdx.x;
    const int lane = tid & 31;
    const int wid  = tid >> 5;                       // 0..31, order == index order
    const int start = start_p[0];
    const int goal  = goal_p[0];
    const float inv_sqrt_n = 1.0f / sqrtf((float)N); // exactly 1/64 for N=4096
    const int Tmax = N / 4;
    const int j0 = tid * VPT;

    // ---- init: g0 = wadj[start] row (diag zeroed), open = {start} ----
    float    h4[VPT];
    unsigned val[VPT];            // key = bits of expf(-f/64) if open else 0
    unsigned openm = 0, histm = 0;
    {
        float4 hv = reinterpret_cast<const float4*>(h_in)[tid];
        float4 g0 = reinterpret_cast<const float4*>(wadj + (size_t)start * N)[tid];
        h4[0] = hv.x; h4[1] = hv.y; h4[2] = hv.z; h4[3] = hv.w;
        float g4[VPT] = {g0.x, g0.y, g0.z, g0.w};
        #pragma unroll
        for (int k = 0; k < VPT; k++) {
            int j = j0 + k;
            float g = (j == start) ? 0.0f : g4[k];
            sm_g[j]   = g;
            sm_par[j] = (unsigned short)goal;        // parents0 = goal
            val[k] = 0u;
            if (j == start) {
                openm |= 1u << k;
                val[k] = __float_as_uint(expf(-(0.5f * g + 0.5f * h4[k]) * inv_sqrt_n));
            }
        }
    }
    __syncthreads();

    bool done = false;
    int  t_final = 0;

    for (int t = 0; t < Tmax; t++) {
        // ---- lane-local best (ascending strict > ==> lowest k on tie) ----
        unsigned bestv = 0u;
        int      bestj = j0;
        #pragma unroll
        for (int k = 0; k < VPT; k++)
            if (val[k] > bestv) { bestv = val[k]; bestj = j0 + k; }

        // ---- warp max; winning (lowest) lane stores directly ----
        unsigned vmax = __reduce_max_sync(0xFFFFFFFFu, bestv);
        unsigned mk   = __ballot_sync(0xFFFFFFFFu, bestv == vmax);
        if (lane == __ffs(mk) - 1)
            sm_warp[t & 1][wid] = make_uint2(vmax, (unsigned)bestj);

        __syncthreads();   // the ONLY barrier per iteration

        // ---- block combine: lane i <- warp i entry; warp order == index order ----
        uint2 e = sm_warp[t & 1][lane];              // 1 LDS.64, conflict-free
        unsigned gv = __reduce_max_sync(0xFFFFFFFFu, e.x);
        unsigned bm = __ballot_sync(0xFFFFFFFFu, e.x == gv);
        const int ind = (int)__shfl_sync(0xFFFFFFFFu, e.y, __ffs(bm) - 1);
        // empty open: all keys 0 -> warp0/lane0 wins with bestj 0 == reference
        // argmax-of-zeros fallback.

        // ---- fetch selected row (L2-warm across graph replays) ----
        const float g_ind = sm_g[ind];    // ind is never relaxed this iteration
        float4 wv = reinterpret_cast<const float4*>(wadj + (size_t)ind * N)[tid];
        float w4a[VPT] = {wv.x, wv.y, wv.z, wv.w};

        t_final = t;
        if (ind == goal) done = true;

        // ---- close ind (open2/hist2) ----
        if ((unsigned)(ind - j0) < VPT) {
            int k = ind - j0;
            openm &= ~(1u << k);
            histm |=  (1u << k);
            val[k] = 0u;
        }
        // ---- relax: idx == neighbor == (w!=0) & !open & !hist ----
        #pragma unroll
        for (int k = 0; k < VPT; k++) {
            float w = w4a[k];
            if (w != 0.0f && !((openm >> k) & 1u) && !((histm >> k) & 1u)) {
                int j = j0 + k;
                float gn = g_ind + w;                // g2 = g[ind] + wadj[ind,j]
                sm_g[j]   = gn;
                sm_par[j] = (unsigned short)ind;
                val[k] = __float_as_uint(expf(-(0.5f * gn + 0.5f * h4[k]) * inv_sqrt_n));
                openm |= 1u << k;                    // open3
            }
        }

        if (done) break;   // uniform branch; state frozen after goal found
    }

    __syncthreads();       // drain final sm_par writes before readout/backtrack

    // ---- outputs: [0,N) hist, [N,2N) path_maps ----
    #pragma unroll
    for (int k = 0; k < VPT; k++) {
        int j = j0 + k;
        out[j]     = ((histm >> k) & 1u) ? 1.0f : 0.0f;
        out[N + j] = 0.0f;
    }
    __syncthreads();

    if (tid == 0) {
        out[N + goal] = 1.0f;                        // path0 = goal one-hot
        int loc = sm_par[goal];
        for (int i = 0; i < t_final; i++) {
            out[N + loc] = 1.0f;
            loc = sm_par[loc];
        }
    }
}

extern "C" void kernel_launch(void* const* d_in, const int* in_sizes, int n_in,
                              void* d_out, int out_size)
{
    const int*   start = (const int*)  d_in[0];
    const int*   goal  = (const int*)  d_in[1];
    const float* h     = (const float*)d_in[2];
    // d_in[3] = nodes (unused), d_in[4] = adj (redundant with wadj != 0)
    const float* wadj  = (const float*)d_in[5];
    float* out = (float*)d_out;
    int N = in_sizes[2];                             // 4096

    astar_persistent_kernel<<<1, TPB>>>(start, goal, h, wadj, out, N);
}

// round 6
// speedup vs baseline: 2.3530x; 1.2381x over previous
#include <cuda_runtime.h>
#include <cstdint>

// Differentiable A* forward, N=4096, Tmax=N/4. Single persistent block, 1024 thr.
// One __syncthreads per iteration. Keys (exp bits) cached in registers, MUFU
// only on relax. Both reduction stages use redux_max + redux_min(index) —
// tie -> lowest index via lane/warp position == index order. Row loaded with
// __ldcg (rows are touched exactly once; skip L1 allocation).

#define NMAX 4096
#define TPB  1024
#define VPT  4          // nodes per thread

__global__ __launch_bounds__(TPB, 1)
void astar_persistent_kernel(const int* __restrict__ start_p,
                             const int* __restrict__ goal_p,
                             const float* __restrict__ h_in,
                             const float* __restrict__ wadj,
                             float* __restrict__ out,
                             int N)
{
    __shared__ float          sm_g[NMAX];
    __shared__ unsigned short sm_par[NMAX];
    __shared__ __align__(16) uint2 sm_warp[2][32];   // (vmax, bestj), x2 parity

    const int tid  = threadIdx.x;
    const int lane = tid & 31;
    const int wid  = tid >> 5;                       // warp order == index order
    const int start = start_p[0];
    const int goal  = goal_p[0];
    const float inv_sqrt_n = 1.0f / sqrtf((float)N); // exactly 1/64 for N=4096
    const int Tmax = N / 4;
    const int j0 = tid * VPT;

    // ---- init: g0 = wadj[start] row (diag zeroed), open = {start} ----
    float    h4[VPT];
    unsigned val[VPT];            // key = bits of expf(-f/64) if open else 0
    unsigned openm = 0, histm = 0;
    {
        float4 hv = reinterpret_cast<const float4*>(h_in)[tid];
        float4 g0 = reinterpret_cast<const float4*>(wadj + (size_t)start * N)[tid];
        h4[0] = hv.x; h4[1] = hv.y; h4[2] = hv.z; h4[3] = hv.w;
        float g4[VPT] = {g0.x, g0.y, g0.z, g0.w};
        #pragma unroll
        for (int k = 0; k < VPT; k++) {
            int j = j0 + k;
            float g = (j == start) ? 0.0f : g4[k];
            sm_g[j]   = g;
            sm_par[j] = (unsigned short)goal;        // parents0 = goal
            val[k] = 0u;
            if (j == start) {
                openm |= 1u << k;
                val[k] = __float_as_uint(expf(-(0.5f * g + 0.5f * h4[k]) * inv_sqrt_n));
            }
        }
    }
    __syncthreads();

    bool done = false;
    int  t_final = 0;

    for (int t = 0; t < Tmax; t++) {
        // ---- lane-local best (ascending strict > ==> lowest k on tie) ----
        unsigned bestv = 0u;
        int      bestj = j0;
        #pragma unroll
        for (int k = 0; k < VPT; k++)
            if (val[k] > bestv) { bestv = val[k]; bestj = j0 + k; }

        // ---- warp stage: max key, then min index among maxima ----
        unsigned vmax = __reduce_max_sync(0xFFFFFFFFu, bestv);
        unsigned jmin = __reduce_min_sync(0xFFFFFFFFu,
                            (bestv == vmax) ? (unsigned)bestj : 0x7FFFFFFFu);
        if (lane == 0) sm_warp[t & 1][wid] = make_uint2(vmax, jmin);

        __syncthreads();   // the ONLY barrier per iteration

        // ---- block combine: lane i <- warp i entry; same dual-redux ----
        uint2 e = sm_warp[t & 1][lane];              // 1 LDS.64, conflict-free
        unsigned gv  = __reduce_max_sync(0xFFFFFFFFu, e.x);
        const int ind = (int)__reduce_min_sync(0xFFFFFFFFu,
                            (e.x == gv) ? e.y : 0x7FFFFFFFu);
        // empty open: all keys 0 -> gv=0, min bestj over warp bases = 0,
        // matching reference argmax-of-zeros fallback.

        // ---- fetch selected row (L2-warm; evict L1 — rows never reused) ----
        const float g_ind = sm_g[ind];    // ind is never relaxed this iteration
        float4 wv = __ldcg(reinterpret_cast<const float4*>(wadj + (size_t)ind * N) + tid);
        float w4a[VPT] = {wv.x, wv.y, wv.z, wv.w};

        t_final = t;
        if (ind == goal) done = true;

        // ---- close ind (open2/hist2) ----
        if ((unsigned)(ind - j0) < VPT) {
            int k = ind - j0;
            openm &= ~(1u << k);
            histm |=  (1u << k);
            val[k] = 0u;
        }
        // ---- relax: idx == neighbor == (w!=0) & free ----
        const unsigned freem = ~(openm | histm);
        #pragma unroll
        for (int k = 0; k < VPT; k++) {
            float w = w4a[k];
            if (w != 0.0f && ((freem >> k) & 1u)) {
                int j = j0 + k;
                float gn = g_ind + w;                // g2 = g[ind] + wadj[ind,j]
                sm_g[j]   = gn;
                sm_par[j] = (unsigned short)ind;
                val[k] = __float_as_uint(expf(-(0.5f * gn + 0.5f * h4[k]) * inv_sqrt_n));
                openm |= 1u << k;                    // open3
            }
        }

        if (done) break;   // uniform branch; state frozen after goal found
    }

    __syncthreads();       // drain final sm_par writes before readout/backtrack

    // ---- outputs: [0,N) hist, [N,2N) path_maps ----
    #pragma unroll
    for (int k = 0; k < VPT; k++) {
        int j = j0 + k;
        out[j]     = ((histm >> k) & 1u) ? 1.0f : 0.0f;
        out[N + j] = 0.0f;
    }
    __syncthreads();

    if (tid == 0) {
        out[N + goal] = 1.0f;                        // path0 = goal one-hot
        int loc = sm_par[goal];
        for (int i = 0; i < t_final; i++) {
            out[N + loc] = 1.0f;
            loc = sm_par[loc];
        }
    }
}

extern "C" void kernel_launch(void* const* d_in, const int* in_sizes, int n_in,
                              void* d_out, int out_size)
{
    const int*   start = (const int*)  d_in[0];
    const int*   goal  = (const int*)  d_in[1];
    const float* h     = (const float*)d_in[2];
    // d_in[3] = nodes (unused), d_in[4] = adj (redundant with wadj != 0)
    const float* wadj  = (const float*)d_in[5];
    float* out = (float*)d_out;
    int N = in_sizes[2];                             // 4096

    astar_persistent_kernel<<<1, TPB>>>(start, goal, h, wadj, out, N);
}